// round 2
// baseline (speedup 1.0000x reference)
#include <cuda_runtime.h>

// LightConv: depthwise conv1d over flat-reinterpreted input.
// x (8,4096,1024) f32 == rows: (512*16, 4096). Row r uses head h = r % 16.
// weight (16,1,7) f32, softmaxed along K before use. pad=3 keeps length 4096.

#define T_LEN 4096
#define HEADS 16
#define KW 7
#define PAD_W 3
#define TILE 1024          // elements per block
#define NTHREADS 256       // TILE/4 threads, float4 per thread
#define TILES_PER_ROW (T_LEN / TILE)   // 4
#define NROWS 8192
#define NBLOCKS (NROWS * TILES_PER_ROW)

__global__ __launch_bounds__(NTHREADS)
void lightconv_kernel(const float* __restrict__ x,
                      const float* __restrict__ weight,
                      float* __restrict__ out) {
    __shared__ float s[TILE + 2 * PAD_W];
    __shared__ float sw[KW];

    const int bid  = blockIdx.x;              // 0..32767
    const int row  = bid >> 2;                // /TILES_PER_ROW
    const int tile = bid & (TILES_PER_ROW - 1);
    const int tid  = threadIdx.x;             // 0..255
    const int h    = row & (HEADS - 1);

    // --- softmax of this head's 7 weights, once per block ---
    if (tid == 0) {
        float wv[KW];
        float m = -1e30f;
        #pragma unroll
        for (int i = 0; i < KW; i++) { wv[i] = weight[h * KW + i]; m = fmaxf(m, wv[i]); }
        float sum = 0.f;
        #pragma unroll
        for (int i = 0; i < KW; i++) { wv[i] = __expf(wv[i] - m); sum += wv[i]; }
        float inv = 1.f / sum;
        #pragma unroll
        for (int i = 0; i < KW; i++) sw[i] = wv[i] * inv;
    }

    const long long row_base = (long long)row * T_LEN;
    const int t0 = tile * TILE;               // tile start within row

    // --- main tile load, float4 coalesced ---
    {
        const float4 v = *reinterpret_cast<const float4*>(x + row_base + t0 + tid * 4);
        s[PAD_W + tid * 4 + 0] = v.x;
        s[PAD_W + tid * 4 + 1] = v.y;
        s[PAD_W + tid * 4 + 2] = v.z;
        s[PAD_W + tid * 4 + 3] = v.w;
    }
    // --- halos (zero beyond row ends) ---
    if (tid < PAD_W) {
        int gl = t0 - PAD_W + tid;
        s[tid] = (gl >= 0) ? x[row_base + gl] : 0.f;
    } else if (tid >= 32 && tid < 32 + PAD_W) {
        int k = tid - 32;
        int gr = t0 + TILE + k;
        s[TILE + PAD_W + k] = (gr < T_LEN) ? x[row_base + gr] : 0.f;
    }
    __syncthreads();

    const float w0 = sw[0], w1 = sw[1], w2 = sw[2], w3 = sw[3],
                w4 = sw[4], w5 = sw[5], w6 = sw[6];

    // Each thread produces 4 outputs; needs s[p-3 .. p+6] (10 values).
    const int p = PAD_W + tid * 4;
    float v[10];
    #pragma unroll
    for (int i = 0; i < 10; i++) v[i] = s[p - 3 + i];

    float4 o;
    o.x = v[0]*w0 + v[1]*w1 + v[2]*w2 + v[3]*w3 + v[4]*w4 + v[5]*w5 + v[6]*w6;
    o.y = v[1]*w0 + v[2]*w1 + v[3]*w2 + v[4]*w3 + v[5]*w4 + v[6]*w5 + v[7]*w6;
    o.z = v[2]*w0 + v[3]*w1 + v[4]*w2 + v[5]*w3 + v[6]*w4 + v[7]*w5 + v[8]*w6;
    o.w = v[3]*w0 + v[4]*w1 + v[5]*w2 + v[6]*w3 + v[7]*w4 + v[8]*w5 + v[9]*w6;

    *reinterpret_cast<float4*>(out + row_base + t0 + tid * 4) = o;
}

extern "C" void kernel_launch(void* const* d_in, const int* in_sizes, int n_in,
                              void* d_out, int out_size) {
    const float* x = (const float*)d_in[0];       // (8,4096,1024) f32
    const float* w = (const float*)d_in[1];       // (16,1,7) f32
    float* out = (float*)d_out;

    lightconv_kernel<<<NBLOCKS, NTHREADS>>>(x, w, out);
}

// round 3
// speedup vs baseline: 1.0375x; 1.0375x over previous
#include <cuda_runtime.h>

// LightConv: depthwise conv1d over flat-reinterpreted input.
// x (8,4096,1024) f32 == rows: (8192, 4096). Row r uses head h = r % 16.
// weight (16,1,7) f32, softmaxed along K before use. pad=3 keeps length 4096.

#define T_LEN 4096
#define HEADS 16
#define KW 7
#define TILE 1024          // elements per block
#define NTHREADS 256       // TILE/4 threads, float4 per thread
#define TILES_PER_ROW (T_LEN / TILE)   // 4
#define NROWS 8192
#define NBLOCKS (NROWS * TILES_PER_ROW)

__global__ __launch_bounds__(NTHREADS)
void lightconv_kernel(const float* __restrict__ x,
                      const float* __restrict__ weight,
                      float* __restrict__ out) {
    // float4-granular shared tile with one float4 halo slot each side.
    // All LDS are aligned LDS.128, consecutive lanes -> consecutive 16B: conflict-free.
    __shared__ float4 sm[NTHREADS + 2];
    __shared__ float sw[KW];

    const int bid  = blockIdx.x;              // 0..32767
    const int row  = bid >> 2;                // /TILES_PER_ROW
    const int tile = bid & (TILES_PER_ROW - 1);
    const int tid  = threadIdx.x;             // 0..255
    const int h    = row & (HEADS - 1);

    // --- softmax of this head's 7 weights, once per block ---
    if (tid == 0) {
        float wv[KW];
        float mx = -1e30f;
        #pragma unroll
        for (int i = 0; i < KW; i++) { wv[i] = weight[h * KW + i]; mx = fmaxf(mx, wv[i]); }
        float sum = 0.f;
        #pragma unroll
        for (int i = 0; i < KW; i++) { wv[i] = __expf(wv[i] - mx); sum += wv[i]; }
        float inv = 1.f / sum;
        #pragma unroll
        for (int i = 0; i < KW; i++) sw[i] = wv[i] * inv;
    }

    const long long row_base = (long long)row * T_LEN;
    const int t0 = tile * TILE;               // tile start within row

    // --- main tile load, float4 coalesced ---
    sm[tid + 1] = *reinterpret_cast<const float4*>(x + row_base + t0 + tid * 4);

    // --- halo float4s (zeroed beyond row ends); aligned 16B loads ---
    if (tid == 0) {
        sm[0] = (t0 > 0)
            ? *reinterpret_cast<const float4*>(x + row_base + t0 - 4)
            : make_float4(0.f, 0.f, 0.f, 0.f);
    } else if (tid == 32) {
        sm[NTHREADS + 1] = (t0 + TILE < T_LEN)
            ? *reinterpret_cast<const float4*>(x + row_base + t0 + TILE)
            : make_float4(0.f, 0.f, 0.f, 0.f);
    }
    __syncthreads();

    const float w0 = sw[0], w1 = sw[1], w2 = sw[2], w3 = sw[3],
                w4 = sw[4], w5 = sw[5], w6 = sw[6];

    // Three conflict-free LDS.128; register shifts cover the +/-3 window.
    const float4 l = sm[tid];
    const float4 m = sm[tid + 1];
    const float4 r = sm[tid + 2];

    float4 o;
    o.x = l.y*w0 + l.z*w1 + l.w*w2 + m.x*w3 + m.y*w4 + m.z*w5 + m.w*w6;
    o.y = l.z*w0 + l.w*w1 + m.x*w2 + m.y*w3 + m.z*w4 + m.w*w5 + r.x*w6;
    o.z = l.w*w0 + m.x*w1 + m.y*w2 + m.z*w3 + m.w*w4 + r.x*w5 + r.y*w6;
    o.w = m.x*w0 + m.y*w1 + m.z*w2 + m.w*w3 + r.x*w4 + r.y*w5 + r.z*w6;

    *reinterpret_cast<float4*>(out + row_base + t0 + tid * 4) = o;
}

extern "C" void kernel_launch(void* const* d_in, const int* in_sizes, int n_in,
                              void* d_out, int out_size) {
    const float* x = (const float*)d_in[0];       // (8,4096,1024) f32
    const float* w = (const float*)d_in[1];       // (16,1,7) f32
    float* out = (float*)d_out;

    lightconv_kernel<<<NBLOCKS, NTHREADS>>>(x, w, out);
}

// round 10
// speedup vs baseline: 1.1989x; 1.1555x over previous
#include <cuda_runtime.h>

// LightConv: depthwise conv1d over flat-reinterpreted input.
// x (8,4096,1024) f32 == rows: (8192, 4096). Row r uses head h = r % 16.
// weight (16,1,7) f32, softmaxed along K before use. pad=3 keeps length 4096.
//
// R4 (resubmit x6 after broker timeouts): one block = one full row.
//  - 4 independent batched LDG.128 per thread (MLP_p1=4) before the single sync
//  - no inter-tile halos (row edges zero-padded in shared)
//  - streaming cache hints (.cs) -- data has zero reuse
//  - conflict-free LDS.128 conv reads (float4-granular shared)

#define T_LEN 4096
#define HEADS 16
#define KW 7
#define NTHREADS 256
#define F4_PER_ROW (T_LEN / 4)            // 1024
#define F4_PER_THREAD (F4_PER_ROW / NTHREADS)  // 4
#define NROWS 8192

__global__ __launch_bounds__(NTHREADS)
void lightconv_kernel(const float* __restrict__ x,
                      const float* __restrict__ weight,
                      float* __restrict__ out) {
    // whole row in shared, float4-granular, one zero halo slot each side
    __shared__ float4 sm[F4_PER_ROW + 2];
    __shared__ float sw[KW];

    const int row = blockIdx.x;               // 0..8191
    const int tid = threadIdx.x;              // 0..255
    const int h   = row & (HEADS - 1);

    // --- softmax of this head's 7 weights, once per block ---
    if (tid == 0) {
        float wv[KW];
        float mx = -1e30f;
        #pragma unroll
        for (int i = 0; i < KW; i++) { wv[i] = weight[h * KW + i]; mx = fmaxf(mx, wv[i]); }
        float sum = 0.f;
        #pragma unroll
        for (int i = 0; i < KW; i++) { wv[i] = __expf(wv[i] - mx); sum += wv[i]; }
        float inv = 1.f / sum;
        #pragma unroll
        for (int i = 0; i < KW; i++) sw[i] = wv[i] * inv;
    } else if (tid == 32) {
        sm[0] = make_float4(0.f, 0.f, 0.f, 0.f);
    } else if (tid == 64) {
        sm[F4_PER_ROW + 1] = make_float4(0.f, 0.f, 0.f, 0.f);
    }

    const long long row_base = (long long)row * T_LEN;
    const float4* xr = reinterpret_cast<const float4*>(x + row_base);

    // --- load whole row: 4 independent streaming LDG.128 per thread ---
    float4 ld[F4_PER_THREAD];
    #pragma unroll
    for (int i = 0; i < F4_PER_THREAD; i++)
        ld[i] = __ldcs(&xr[i * NTHREADS + tid]);
    #pragma unroll
    for (int i = 0; i < F4_PER_THREAD; i++)
        sm[1 + i * NTHREADS + tid] = ld[i];

    __syncthreads();

    const float w0 = sw[0], w1 = sw[1], w2 = sw[2], w3 = sw[3],
                w4 = sw[4], w5 = sw[5], w6 = sw[6];

    float4* orow = reinterpret_cast<float4*>(out + row_base);

    #pragma unroll
    for (int i = 0; i < F4_PER_THREAD; i++) {
        const int j = i * NTHREADS + tid;     // output float4 index in row
        const float4 l = sm[j];
        const float4 m = sm[j + 1];
        const float4 r = sm[j + 2];

        float4 o;
        o.x = l.y*w0 + l.z*w1 + l.w*w2 + m.x*w3 + m.y*w4 + m.z*w5 + m.w*w6;
        o.y = l.z*w0 + l.w*w1 + m.x*w2 + m.y*w3 + m.z*w4 + m.w*w5 + r.x*w6;
        o.z = l.w*w0 + m.x*w1 + m.y*w2 + m.z*w3 + m.w*w4 + r.x*w5 + r.y*w6;
        o.w = m.x*w0 + m.y*w1 + m.z*w2 + m.w*w3 + r.x*w4 + r.y*w5 + r.z*w6;

        __stcs(&orow[j], o);
    }
}

extern "C" void kernel_launch(void* const* d_in, const int* in_sizes, int n_in,
                              void* d_out, int out_size) {
    const float* x = (const float*)d_in[0];       // (8,4096,1024) f32
    const float* w = (const float*)d_in[1];       // (16,1,7) f32
    float* out = (float*)d_out;

    lightconv_kernel<<<NROWS, NTHREADS>>>(x, w, out);
}